// round 1
// baseline (speedup 1.0000x reference)
#include <cuda_runtime.h>

#define Bv 4
#define Nv 512
#define Dv 256
#define Lv 64

// Scratch for projected features, transposed layout [b][l][n]  (512 KB)
__device__ float g_xh[Bv * Lv * Nv];

// ---------------------------------------------------------------------------
// Kernel 1: x_hat[b,n,l] = sum_d x[b,n,d] * W[l,d], written as g_xh[b][l][n]
// Block: 16 rows (n) x all 64 l.  256 threads, each computes 4 outputs.
// ---------------------------------------------------------------------------
__global__ __launch_bounds__(256) void proj_kernel(const float* __restrict__ x,
                                                   const float* __restrict__ W) {
    extern __shared__ float sm[];
    float* xs = sm;                 // [256][17]  x tile transposed, padded
    float* Wt = sm + 256 * 17;      // [256][68]  W transposed, padded

    int b  = blockIdx.x >> 5;           // 32 tiles per batch
    int n0 = (blockIdx.x & 31) << 4;    // 16 rows per tile
    int tid = threadIdx.x;

    // load x tile (coalesced), store transposed [d][r] with pad 17
    for (int idx = tid; idx < 16 * 256; idx += 256) {
        int rr = idx >> 8, d = idx & 255;
        xs[d * 17 + rr] = x[(b * Nv + n0 + rr) * Dv + d];
    }
    // load W (coalesced), store transposed [d][l] with pad 68
    for (int idx = tid; idx < 64 * 256; idx += 256) {
        int l = idx >> 8, d = idx & 255;
        Wt[d * 68 + l] = W[l * Dv + d];
    }
    __syncthreads();

    int r  = tid & 15;
    int l0 = (tid >> 4) << 2;   // 4 consecutive l per thread

    float a0 = 0.f, a1 = 0.f, a2 = 0.f, a3 = 0.f;
#pragma unroll 8
    for (int d = 0; d < 256; ++d) {
        float  xv = xs[d * 17 + r];
        float4 wq = *(const float4*)&Wt[d * 68 + l0];
        a0 = fmaf(xv, wq.x, a0);
        a1 = fmaf(xv, wq.y, a1);
        a2 = fmaf(xv, wq.z, a2);
        a3 = fmaf(xv, wq.w, a3);
    }
    float* dst = g_xh + b * (Lv * Nv) + n0 + r;
    dst[(l0 + 0) * Nv] = a0;
    dst[(l0 + 1) * Nv] = a1;
    dst[(l0 + 2) * Nv] = a2;
    dst[(l0 + 3) * Nv] = a3;
}

// ---------------------------------------------------------------------------
// Kernel 2: dist + leaky_relu + row-softmax-style normalization, fully fused.
// Block: (b, tile of 16 i-rows). 256 threads = 8 warps, each warp owns 2 rows.
// smem holds the full x_hat[b] as [l][n] (128 KB) + per-tile i-rows [i][l].
// ---------------------------------------------------------------------------
__global__ __launch_bounds__(256, 1) void dist_softmax_kernel(
    const float* __restrict__ adj, const float* __restrict__ lw,
    float* __restrict__ out) {
    extern __shared__ float sm[];
    float* sj = sm;                      // [64][512] x_hat[b], l-major
    float* si = sm + Lv * Nv;            // [16][64]  this tile's i rows, l fast
    float* ws = si + 16 * 64;            // [64]      learn_w

    int b  = blockIdx.x >> 5;
    int i0 = (blockIdx.x & 31) << 4;
    int tid = threadIdx.x;

    const float* xh = g_xh + b * (Lv * Nv);
    for (int idx = tid; idx < (Lv * Nv) / 4; idx += 256)
        ((float4*)sj)[idx] = ((const float4*)xh)[idx];
    for (int idx = tid; idx < 16 * 64; idx += 256) {
        int il = idx >> 6, l = idx & 63;
        si[idx] = xh[l * Nv + i0 + il];
    }
    if (tid < 64) ws[tid] = lw[tid];
    __syncthreads();

    int w    = tid >> 5;
    int lane = tid & 31;
    int ia = i0 + 2 * w;
    int ib = ia + 1;
    const float* pa = si + (2 * w) * 64;
    const float* pb = pa + 64;

    float da[16], db[16];

#pragma unroll
    for (int g = 0; g < 4; ++g) {
        int j0 = g * 128 + lane * 4;
        float aa[4] = {0.f, 0.f, 0.f, 0.f};
        float ab[4] = {0.f, 0.f, 0.f, 0.f};
#pragma unroll
        for (int l4 = 0; l4 < 16; ++l4) {
            float4 wv4 = *(const float4*)&ws[l4 * 4];
            float4 va4 = *(const float4*)&pa[l4 * 4];
            float4 vb4 = *(const float4*)&pb[l4 * 4];
            const float* wp  = (const float*)&wv4;
            const float* vap = (const float*)&va4;
            const float* vbp = (const float*)&vb4;
#pragma unroll
            for (int c = 0; c < 4; ++c) {
                int l = l4 * 4 + c;
                float4 jv = *(const float4*)&sj[l * Nv + j0];
                float wc = wp[c], va = vap[c], vb = vbp[c];
                aa[0] = fmaf(wc, fabsf(jv.x - va), aa[0]);
                aa[1] = fmaf(wc, fabsf(jv.y - va), aa[1]);
                aa[2] = fmaf(wc, fabsf(jv.z - va), aa[2]);
                aa[3] = fmaf(wc, fabsf(jv.w - va), aa[3]);
                ab[0] = fmaf(wc, fabsf(jv.x - vb), ab[0]);
                ab[1] = fmaf(wc, fabsf(jv.y - vb), ab[1]);
                ab[2] = fmaf(wc, fabsf(jv.z - vb), ab[2]);
                ab[3] = fmaf(wc, fabsf(jv.w - vb), ab[3]);
            }
        }
        da[g * 4 + 0] = aa[0]; da[g * 4 + 1] = aa[1];
        da[g * 4 + 2] = aa[2]; da[g * 4 + 3] = aa[3];
        db[g * 4 + 0] = ab[0]; db[g * 4 + 1] = ab[1];
        db[g * 4 + 2] = ab[2]; db[g * 4 + 3] = ab[3];
    }

    // leaky_relu + per-row max
    float ma = -1e30f, mb = -1e30f;
#pragma unroll
    for (int k = 0; k < 16; ++k) {
        float d = da[k]; d = d > 0.f ? d : 0.01f * d; da[k] = d; ma = fmaxf(ma, d);
        float e = db[k]; e = e > 0.f ? e : 0.01f * e; db[k] = e; mb = fmaxf(mb, e);
    }
#pragma unroll
    for (int o = 16; o; o >>= 1) {
        ma = fmaxf(ma, __shfl_xor_sync(0xffffffffu, ma, o));
        mb = fmaxf(mb, __shfl_xor_sync(0xffffffffu, mb, o));
    }

    // adj * exp(d - max), row sums
    const float* adja = adj + (size_t)(b * Nv + ia) * Nv;
    const float* adjb = adj + (size_t)(b * Nv + ib) * Nv;
    float sa = 0.f, sb = 0.f;
#pragma unroll
    for (int g = 0; g < 4; ++g) {
        int j0 = g * 128 + lane * 4;
        float4 av = *(const float4*)&adja[j0];
        float4 bv = *(const float4*)&adjb[j0];
        float v;
        v = av.x * __expf(da[g*4+0] - ma); da[g*4+0] = v; sa += v;
        v = av.y * __expf(da[g*4+1] - ma); da[g*4+1] = v; sa += v;
        v = av.z * __expf(da[g*4+2] - ma); da[g*4+2] = v; sa += v;
        v = av.w * __expf(da[g*4+3] - ma); da[g*4+3] = v; sa += v;
        v = bv.x * __expf(db[g*4+0] - mb); db[g*4+0] = v; sb += v;
        v = bv.y * __expf(db[g*4+1] - mb); db[g*4+1] = v; sb += v;
        v = bv.z * __expf(db[g*4+2] - mb); db[g*4+2] = v; sb += v;
        v = bv.w * __expf(db[g*4+3] - mb); db[g*4+3] = v; sb += v;
    }
#pragma unroll
    for (int o = 16; o; o >>= 1) {
        sa += __shfl_xor_sync(0xffffffffu, sa, o);
        sb += __shfl_xor_sync(0xffffffffu, sb, o);
    }
    float ra = 1.0f / sa;
    float rb = 1.0f / sb;

    float* oa = out + (size_t)(b * Nv + ia) * Nv;
    float* ob = out + (size_t)(b * Nv + ib) * Nv;
#pragma unroll
    for (int g = 0; g < 4; ++g) {
        int j0 = g * 128 + lane * 4;
        float4 o4;
        o4.x = da[g*4+0] * ra + 1e-10f;
        o4.y = da[g*4+1] * ra + 1e-10f;
        o4.z = da[g*4+2] * ra + 1e-10f;
        o4.w = da[g*4+3] * ra + 1e-10f;
        *(float4*)&oa[j0] = o4;
        o4.x = db[g*4+0] * rb + 1e-10f;
        o4.y = db[g*4+1] * rb + 1e-10f;
        o4.z = db[g*4+2] * rb + 1e-10f;
        o4.w = db[g*4+3] * rb + 1e-10f;
        *(float4*)&ob[j0] = o4;
    }
}

extern "C" void kernel_launch(void* const* d_in, const int* in_sizes, int n_in,
                              void* d_out, int out_size) {
    (void)in_sizes; (void)n_in; (void)out_size;
    const float* x   = (const float*)d_in[0];
    const float* adj = (const float*)d_in[1];
    const float* W   = (const float*)d_in[2];
    const float* lw  = (const float*)d_in[3];
    float* out = (float*)d_out;

    const int smem1 = (256 * 17 + 256 * 68) * 4;            // 87040 B
    const int smem2 = (Lv * Nv + 16 * 64 + 64) * 4;         // 135424 B
    cudaFuncSetAttribute(proj_kernel,
                         cudaFuncAttributeMaxDynamicSharedMemorySize, smem1);
    cudaFuncSetAttribute(dist_softmax_kernel,
                         cudaFuncAttributeMaxDynamicSharedMemorySize, smem2);

    proj_kernel<<<Bv * (Nv / 16), 256, smem1>>>(x, W);
    dist_softmax_kernel<<<Bv * (Nv / 16), 256, smem2>>>(adj, lw, out);
}